// round 14
// baseline (speedup 1.0000x reference)
#include <cuda_runtime.h>

// Shapes: (64, 4, 256, 256) f32.
#define B 64
#define PER_BATCH (4 * 256 * 256)   // 262144
#define MARGIN 1.0f
#define NUM_PAIRS (B * (B - 1) / 2) // 2016

#define THREADS 256
#define VEC_PER_THREAD 4                                  // float4s per thread per stream
#define ELEMS_PER_CHUNK (THREADS * VEC_PER_THREAD * 4)    // 4096
#define CHUNKS_PER_BATCH (PER_BATCH / ELEMS_PER_CHUNK)    // 64

// Role split: err-blocks read pm+tg (2 streams, 1 chunk each = 32KB);
//             unc-blocks read ps (1 stream, 2 chunks = 32KB).
#define GRID_E (B * CHUNKS_PER_BATCH)                     // 4096
#define GRID_U (GRID_E / 2)                               // 2048
#define GRID   (GRID_E + GRID_U)                          // 6144
#define UCHUNKS_PER_BATCH (CHUNKS_PER_BATCH / 2)          // 32 double-chunks/batch

// Device-global scratch (zero-init at load; self-reset every launch).
__device__ float        g_err[B];
__device__ float        g_unc[B];
__device__ unsigned int g_arrived;

__global__ __launch_bounds__(THREADS)
void fused_kernel(const float* __restrict__ pm,
                  const float* __restrict__ ps,
                  const float* __restrict__ tg,
                  float* __restrict__ out) {
    int lane = threadIdx.x & 31;
    int wid  = threadIdx.x >> 5;
    __shared__ float sred[THREADS / 32];

    float acc = 0.0f;
    int batch;
    float* gdst;

    if (blockIdx.x < GRID_E) {
        // ── err role: |pm - tg| over one 4096-elem chunk ────────────────
        int chunk = blockIdx.x;
        batch = chunk / CHUNKS_PER_BATCH;
        size_t base = (size_t)chunk * ELEMS_PER_CHUNK;
        const float4* pm4 = (const float4*)(pm + base);
        const float4* tg4 = (const float4*)(tg + base);
        #pragma unroll
        for (int i = 0; i < VEC_PER_THREAD; i++) {
            int idx = threadIdx.x + i * THREADS;   // coalesced
            float4 a = __ldcs(&pm4[idx]);
            float4 t = __ldcs(&tg4[idx]);
            acc += fabsf(a.x - t.x) + fabsf(a.y - t.y)
                 + fabsf(a.z - t.z) + fabsf(a.w - t.w);
        }
        gdst = &g_err[0];
    } else {
        // ── unc role: sum ps over one 8192-elem double-chunk ────────────
        int uchunk = blockIdx.x - GRID_E;
        batch = uchunk / UCHUNKS_PER_BATCH;
        size_t base = (size_t)uchunk * (2 * ELEMS_PER_CHUNK);
        const float4* ps4 = (const float4*)(ps + base);
        #pragma unroll
        for (int i = 0; i < 2 * VEC_PER_THREAD; i++) {
            int idx = threadIdx.x + i * THREADS;   // coalesced, single stream
            float4 s = __ldcs(&ps4[idx]);
            acc += s.x + s.y + s.z + s.w;
        }
        gdst = &g_unc[0];
    }

    // ── block reduce (one scalar) ───────────────────────────────────────
    #pragma unroll
    for (int off = 16; off > 0; off >>= 1)
        acc += __shfl_down_sync(0xFFFFFFFFu, acc, off);
    if (lane == 0) sred[wid] = acc;
    __syncthreads();
    if (wid == 0) {
        acc = (lane < THREADS / 32) ? sred[lane] : 0.0f;
        #pragma unroll
        for (int off = 4; off > 0; off >>= 1)
            acc += __shfl_down_sync(0xFFFFFFFFu, acc, off);
        if (lane == 0)
            atomicAdd(&gdst[batch], acc);
    }

    // ── last-block-arrival finalize ─────────────────────────────────────
    __shared__ unsigned int s_is_last;
    __syncthreads();                 // this block's atomic has been issued
    if (threadIdx.x == 0) {
        __threadfence();             // make this block's add globally visible
        unsigned int n = atomicAdd(&g_arrived, 1u);
        s_is_last = (n == GRID - 1u) ? 1u : 0u;
    }
    __syncthreads();
    if (s_is_last == 0u) return;

    __threadfence();                 // order counter observation before accumulator reads

    __shared__ float err_s[B], unc_s[B];
    int i = threadIdx.x;
    if (i < B) {
        const float inv_n = 1.0f / (float)PER_BATCH;
        err_s[i] = __ldcg(&g_err[i]) * inv_n;
        unc_s[i] = __ldcg(&g_unc[i]) * inv_n;
    }
    __syncthreads();

    if (i < B) {
        float ei = err_s[i], ui = unc_s[i];
        float sum = 0.0f;
        #pragma unroll 4
        for (int j = i + 1; j < B; j++) {
            float ej = err_s[j], uj = unc_s[j];
            float d = (ei > ej) ? (uj - ui) : (ui - uj);
            sum += fmaxf(d + MARGIN, 0.0f);
        }
        #pragma unroll
        for (int off = 16; off > 0; off >>= 1)
            sum += __shfl_down_sync(0xFFFFFFFFu, sum, off);

        __shared__ float ws[2];
        if ((i & 31) == 0) ws[i >> 5] = sum;
        __syncthreads();
        if (i == 0) out[0] = (ws[0] + ws[1]) / (float)NUM_PAIRS;

        // reset scratch for the next graph replay
        __stcg(&g_err[i], 0.0f);
        __stcg(&g_unc[i], 0.0f);
        if (i == 0) { __threadfence(); g_arrived = 0u; }
    }
}

extern "C" void kernel_launch(void* const* d_in, const int* in_sizes, int n_in,
                              void* d_out, int out_size) {
    const float* pred_mean = (const float*)d_in[0];
    const float* pred_std  = (const float*)d_in[1];
    const float* targets   = (const float*)d_in[2];
    fused_kernel<<<GRID, THREADS>>>(pred_mean, pred_std, targets, (float*)d_out);
}